// round 1
// baseline (speedup 1.0000x reference)
#include <cuda_runtime.h>

// Problem constants (fixed by reference setup_inputs)
#define B_SZ 16
#define S_SZ 4096
#define D_SZ 512
#define PE_DIM 256
#define VEC_PER_ROW (D_SZ / 4)       // 128 float4 per (b,s) row
#define PE_VEC_PER_ROW (PE_DIM / 4)  // 64 float4 per pe row

// Scratch: per-batch lengths (no cudaMalloc allowed)
__device__ int g_lengths[B_SZ];

// ---------------------------------------------------------------------------
// Kernel 1: lengths[b] = sum over s of (mask[b,s] == 0)
// ---------------------------------------------------------------------------
__global__ void lengths_kernel(const int* __restrict__ mask) {
    const int b = blockIdx.x;
    const int* m = mask + b * S_SZ;
    int sum = 0;
    for (int s = threadIdx.x; s < S_SZ; s += blockDim.x)
        sum += (m[s] == 0);

    // warp reduce
    #pragma unroll
    for (int off = 16; off > 0; off >>= 1)
        sum += __shfl_down_sync(0xFFFFFFFFu, sum, off);

    __shared__ int warp_sums[8];
    const int lane = threadIdx.x & 31;
    const int wid  = threadIdx.x >> 5;
    if (lane == 0) warp_sums[wid] = sum;
    __syncthreads();
    if (wid == 0) {
        int v = (lane < (blockDim.x >> 5)) ? warp_sums[lane] : 0;
        #pragma unroll
        for (int off = 16; off > 0; off >>= 1)
            v += __shfl_down_sync(0xFFFFFFFFu, v, off);
        if (lane == 0) g_lengths[b] = v;
    }
}

// ---------------------------------------------------------------------------
// Kernel 2: out = x + base_pe + (valid ? reversed-feature pe : 0)
// One float4 per thread. pe is 5.1 MB -> L2-resident after wave 1.
// ---------------------------------------------------------------------------
__global__ void __launch_bounds__(256) add_pe_kernel(
    const float4* __restrict__ x,
    const float4* __restrict__ pe,   // (5000, 64) float4
    float4* __restrict__ out
) {
    const int i = blockIdx.x * blockDim.x + threadIdx.x;
    // i in [0, B*S*128)
    const int c   = i & (VEC_PER_ROW - 1);   // float4 idx within D row
    const int sb  = i >> 7;                  // b * S + s
    const int s   = sb & (S_SZ - 1);
    const int b   = sb >> 12;

    const int chunk4 = c & (PE_VEC_PER_ROW - 1);  // (d0 & 255) / 4

    float4 xv    = x[i];
    float4 basev = pe[s * PE_VEC_PER_ROW + chunk4];

    float4 o;
    o.x = xv.x + basev.x;
    o.y = xv.y + basev.y;
    o.z = xv.z + basev.z;
    o.w = xv.w + basev.w;

    const int L = g_lengths[b];
    if (s < L) {
        // reversed feature indices 255-d .. 252-d == float4 at (63-chunk4), reversed lanes
        const int row = L - 1 - s;  // >= 0 because s < L
        float4 rv = pe[row * PE_VEC_PER_ROW + (PE_VEC_PER_ROW - 1 - chunk4)];
        o.x += rv.w;
        o.y += rv.z;
        o.z += rv.y;
        o.w += rv.x;
    }
    out[i] = o;
}

// ---------------------------------------------------------------------------
// Launch
// d_in[0] = x    (float32, 16*4096*512)
// d_in[1] = mask (int32,   16*4096)
// d_in[2] = pe   (float32, 5000*256)
// ---------------------------------------------------------------------------
extern "C" void kernel_launch(void* const* d_in, const int* in_sizes, int n_in,
                              void* d_out, int out_size) {
    const float* x    = (const float*)d_in[0];
    const int*   mask = (const int*)d_in[1];
    const float* pe   = (const float*)d_in[2];
    float* out = (float*)d_out;

    lengths_kernel<<<B_SZ, 256>>>(mask);

    const int total_vec = B_SZ * S_SZ * VEC_PER_ROW;  // 8,388,608
    const int threads = 256;
    const int blocks = total_vec / threads;           // 32768
    add_pe_kernel<<<blocks, threads>>>(
        (const float4*)x, (const float4*)pe, (float4*)out);
}

// round 2
// speedup vs baseline: 1.0449x; 1.0449x over previous
#include <cuda_runtime.h>

// Problem constants (fixed by reference setup_inputs)
#define B_SZ 16
#define S_SZ 4096
#define D_SZ 512
#define PE_DIM 256
#define VEC_PER_ROW (D_SZ / 4)       // 128 float4 per (b,s) row
#define PE_VEC_PER_ROW (PE_DIM / 4)  // 64 float4 per pe row
#define ILP 4

// Scratch: per-batch lengths (no cudaMalloc allowed)
__device__ int g_lengths[B_SZ];

// ---------------------------------------------------------------------------
// Kernel 1: lengths[b] = sum over s of (mask[b,s] == 0)
// int4-vectorized: 256 threads * 4 int4 = 4096 ints per block, 1 block per b.
// ---------------------------------------------------------------------------
__global__ void __launch_bounds__(256) lengths_kernel(const int4* __restrict__ mask) {
    const int b = blockIdx.x;
    const int4* m = mask + b * (S_SZ / 4);

    int sum = 0;
    #pragma unroll
    for (int k = 0; k < 4; k++) {
        int4 v = m[k * 256 + threadIdx.x];
        sum += (v.x == 0) + (v.y == 0) + (v.z == 0) + (v.w == 0);
    }

    // warp reduce
    #pragma unroll
    for (int off = 16; off > 0; off >>= 1)
        sum += __shfl_down_sync(0xFFFFFFFFu, sum, off);

    __shared__ int warp_sums[8];
    const int lane = threadIdx.x & 31;
    const int wid  = threadIdx.x >> 5;
    if (lane == 0) warp_sums[wid] = sum;
    __syncthreads();
    if (wid == 0) {
        int v = (lane < 8) ? warp_sums[lane] : 0;
        #pragma unroll
        for (int off = 4; off > 0; off >>= 1)
            v += __shfl_down_sync(0xFFFFFFFFu, v, off);
        if (lane == 0) g_lengths[b] = v;
    }
}

// ---------------------------------------------------------------------------
// Kernel 2: out = x + base_pe + (valid ? reversed-feature pe : 0)
// 4 float4 per thread, x loads front-batched (MLP_p1=4).
// x read-once -> __ldcs; out write-once -> __stcs; pe stays L2-resident.
// ---------------------------------------------------------------------------
__global__ void __launch_bounds__(256) add_pe_kernel(
    const float4* __restrict__ x,
    const float4* __restrict__ pe,   // (5000, 64) float4
    float4* __restrict__ out
) {
    const int base = blockIdx.x * (256 * ILP) + threadIdx.x;

    // Front-batch all x loads (independent, streaming)
    float4 xv[ILP];
    #pragma unroll
    for (int k = 0; k < ILP; k++)
        xv[k] = __ldcs(&x[base + k * 256]);

    float4 o[ILP];
    #pragma unroll
    for (int k = 0; k < ILP; k++) {
        const int i  = base + k * 256;
        const int c  = i & (VEC_PER_ROW - 1);
        const int sb = i >> 7;                   // b * S + s
        const int s  = sb & (S_SZ - 1);
        const int b  = sb >> 12;
        const int chunk4 = c & (PE_VEC_PER_ROW - 1);

        const float4 basev = pe[s * PE_VEC_PER_ROW + chunk4];
        o[k].x = xv[k].x + basev.x;
        o[k].y = xv[k].y + basev.y;
        o[k].z = xv[k].z + basev.z;
        o[k].w = xv[k].w + basev.w;

        const int L = g_lengths[b];
        if (s < L) {
            const int row = L - 1 - s;  // >= 0 because s < L
            const float4 rv = pe[row * PE_VEC_PER_ROW + (PE_VEC_PER_ROW - 1 - chunk4)];
            o[k].x += rv.w;
            o[k].y += rv.z;
            o[k].z += rv.y;
            o[k].w += rv.x;
        }
    }

    #pragma unroll
    for (int k = 0; k < ILP; k++)
        __stcs(&out[base + k * 256], o[k]);
}

// ---------------------------------------------------------------------------
// d_in[0] = x (f32, 16*4096*512), d_in[1] = mask (i32, 16*4096),
// d_in[2] = pe (f32, 5000*256)
// ---------------------------------------------------------------------------
extern "C" void kernel_launch(void* const* d_in, const int* in_sizes, int n_in,
                              void* d_out, int out_size) {
    const float* x    = (const float*)d_in[0];
    const int*   mask = (const int*)d_in[1];
    const float* pe   = (const float*)d_in[2];
    float* out = (float*)d_out;

    lengths_kernel<<<B_SZ, 256>>>((const int4*)mask);

    const int total_vec = B_SZ * S_SZ * VEC_PER_ROW;        // 8,388,608
    const int blocks = total_vec / (256 * ILP);             // 8192
    add_pe_kernel<<<blocks, 256>>>(
        (const float4*)x, (const float4*)pe, (float4*)out);
}

// round 3
// speedup vs baseline: 1.0561x; 1.0106x over previous
#include <cuda_runtime.h>

// Problem constants (fixed by reference setup_inputs)
#define B_SZ 16
#define S_SZ 4096
#define D_SZ 512
#define PE_DIM 256
#define VEC_PER_ROW (D_SZ / 4)       // 128 float4 per (b,s) row
#define PE_VEC_PER_ROW (PE_DIM / 4)  // 64 float4 per pe row
#define ILP 4
#define BLOCKS_PER_BATCH 512         // (S_SZ * VEC_PER_ROW) / (256 * ILP) / B... = 4096*128/(1024)/... see below

// Scratch: per-batch lengths (no cudaMalloc allowed)
__device__ int g_lengths[B_SZ];

// ---------------------------------------------------------------------------
// Kernel 1: lengths[b] = sum over s of (mask[b,s] == 0)
// 16 blocks x 1024 threads, one int4 per thread -> single load round-trip.
// ---------------------------------------------------------------------------
__global__ void __launch_bounds__(1024) lengths_kernel(const int4* __restrict__ mask) {
    const int b = blockIdx.x;
    int4 v = mask[b * (S_SZ / 4) + threadIdx.x];
    int sum = (v.x == 0) + (v.y == 0) + (v.z == 0) + (v.w == 0);

    #pragma unroll
    for (int off = 16; off > 0; off >>= 1)
        sum += __shfl_down_sync(0xFFFFFFFFu, sum, off);

    __shared__ int warp_sums[32];
    const int lane = threadIdx.x & 31;
    const int wid  = threadIdx.x >> 5;
    if (lane == 0) warp_sums[wid] = sum;
    __syncthreads();
    if (wid == 0) {
        int s = warp_sums[lane];
        #pragma unroll
        for (int off = 16; off > 0; off >>= 1)
            s += __shfl_down_sync(0xFFFFFFFFu, s, off);
        if (lane == 0) g_lengths[b] = s;
    }
}

// ---------------------------------------------------------------------------
// Kernel 2: out = x + base_pe + (valid ? reversed-feature pe : 0)
// PDL secondary: issues x + base-pe loads, THEN waits on the lengths kernel.
// Each block covers 8 consecutive s-rows inside a single batch
// (512 blocks per batch), so L is uniform per block.
// ---------------------------------------------------------------------------
__global__ void __launch_bounds__(256) add_pe_kernel(
    const float4* __restrict__ x,
    const float4* __restrict__ pe,   // (5000, 64) float4
    float4* __restrict__ out
) {
    const int base = blockIdx.x * (256 * ILP) + threadIdx.x;

    // Front-batch all x loads (independent, streaming, evict-first)
    float4 xv[ILP];
    #pragma unroll
    for (int k = 0; k < ILP; k++)
        xv[k] = __ldcs(&x[base + k * 256]);

    // Base-pe loads + partial sums (independent of g_lengths)
    int s_arr[ILP], c4_arr[ILP];
    float4 o[ILP];
    #pragma unroll
    for (int k = 0; k < ILP; k++) {
        const int i  = base + k * 256;
        const int c  = i & (VEC_PER_ROW - 1);
        const int sb = i >> 7;
        s_arr[k]  = sb & (S_SZ - 1);
        c4_arr[k] = c & (PE_VEC_PER_ROW - 1);

        const float4 basev = pe[s_arr[k] * PE_VEC_PER_ROW + c4_arr[k]];
        o[k].x = xv[k].x + basev.x;
        o[k].y = xv[k].y + basev.y;
        o[k].z = xv[k].z + basev.z;
        o[k].w = xv[k].w + basev.w;
    }

    // Now we need the lengths: wait for the primary (lengths) kernel.
    asm volatile("griddepcontrol.wait;" ::: "memory");
    const int L = g_lengths[blockIdx.x >> 9];   // 512 blocks per batch

    #pragma unroll
    for (int k = 0; k < ILP; k++) {
        if (s_arr[k] < L) {
            const int row = L - 1 - s_arr[k];   // >= 0 because s < L
            const float4 rv = pe[row * PE_VEC_PER_ROW + (PE_VEC_PER_ROW - 1 - c4_arr[k])];
            o[k].x += rv.w;
            o[k].y += rv.z;
            o[k].z += rv.y;
            o[k].w += rv.x;
        }
    }

    #pragma unroll
    for (int k = 0; k < ILP; k++)
        __stcs(&out[base + k * 256], o[k]);
}

// ---------------------------------------------------------------------------
// d_in[0] = x (f32, 16*4096*512), d_in[1] = mask (i32, 16*4096),
// d_in[2] = pe (f32, 5000*256)
// ---------------------------------------------------------------------------
extern "C" void kernel_launch(void* const* d_in, const int* in_sizes, int n_in,
                              void* d_out, int out_size) {
    const float* x    = (const float*)d_in[0];
    const int*   mask = (const int*)d_in[1];
    const float* pe   = (const float*)d_in[2];
    float* out = (float*)d_out;

    lengths_kernel<<<B_SZ, 1024>>>((const int4*)mask);

    const int total_vec = B_SZ * S_SZ * VEC_PER_ROW;        // 8,388,608
    const int blocks = total_vec / (256 * ILP);             // 8192

    // PDL: launch main kernel as a programmatic dependent of lengths_kernel.
    cudaLaunchConfig_t cfg = {};
    cfg.gridDim  = dim3(blocks, 1, 1);
    cfg.blockDim = dim3(256, 1, 1);
    cfg.dynamicSmemBytes = 0;
    cfg.stream = 0;
    cudaLaunchAttribute attrs[1];
    attrs[0].id = cudaLaunchAttributeProgrammaticStreamSerialization;
    attrs[0].val.programmaticStreamSerializationAllowed = 1;
    cfg.attrs = attrs;
    cfg.numAttrs = 1;
    cudaLaunchKernelEx(&cfg, add_pe_kernel,
                       (const float4*)x, (const float4*)pe, (float4*)out);
}

// round 4
// speedup vs baseline: 1.0644x; 1.0079x over previous
#include <cuda_runtime.h>

// Problem constants (fixed by reference setup_inputs)
#define B_SZ 16
#define S_SZ 4096
#define D_SZ 512
#define PE_DIM 256
#define VEC_PER_ROW (D_SZ / 4)       // 128 float4 per (b,s) row
#define PE_VEC_PER_ROW (PE_DIM / 4)  // 64 float4 per pe row
#define ILP 4
// block = 256 threads, ILP 4 -> 1024 float4 = 8 (b,s) rows per block
// 512 blocks per batch -> b = blockIdx.x >> 9 (uniform within block)

// ---------------------------------------------------------------------------
// Fused kernel: each block computes its batch's length from the L2-resident
// mask (16 KB/row), then does out = x + base_pe + (valid ? rev_pe : 0).
// Load schedule: x (DRAM, streaming) -> mask (L2) -> base pe (L2) -> reduce
// -> rev pe (L2) -> store. The block reduction hides under the memory overlap
// of 8 resident blocks/SM.
// ---------------------------------------------------------------------------
__global__ void __launch_bounds__(256) fused_pe_kernel(
    const float4* __restrict__ x,
    const int4*   __restrict__ mask,  // (16, 1024) int4
    const float4* __restrict__ pe,    // (5000, 64) float4
    float4* __restrict__ out
) {
    const int tid  = threadIdx.x;
    const int base = blockIdx.x * (256 * ILP) + tid;
    const int b    = blockIdx.x >> 9;            // 512 blocks per batch

    // 1) Front-batch all x loads (independent, streaming, evict-first)
    float4 xv[ILP];
    #pragma unroll
    for (int k = 0; k < ILP; k++)
        xv[k] = __ldcs(&x[base + k * 256]);

    // 2) Mask loads for this batch (L2-resident after wave 1)
    const int4* m = mask + b * (S_SZ / 4);
    int4 mv[4];
    #pragma unroll
    for (int k = 0; k < 4; k++)
        mv[k] = __ldg(&m[k * 256 + tid]);

    // 3) Base-pe loads + partial sums (independent of L)
    int s_arr[ILP], c4_arr[ILP];
    float4 o[ILP];
    #pragma unroll
    for (int k = 0; k < ILP; k++) {
        const int i  = base + k * 256;
        const int c  = i & (VEC_PER_ROW - 1);
        const int sb = i >> 7;
        s_arr[k]  = sb & (S_SZ - 1);
        c4_arr[k] = c & (PE_VEC_PER_ROW - 1);

        const float4 basev = pe[s_arr[k] * PE_VEC_PER_ROW + c4_arr[k]];
        o[k].x = xv[k].x + basev.x;
        o[k].y = xv[k].y + basev.y;
        o[k].z = xv[k].z + basev.z;
        o[k].w = xv[k].w + basev.w;
    }

    // 4) Block-reduce mask==0 count -> L
    int sum = 0;
    #pragma unroll
    for (int k = 0; k < 4; k++)
        sum += (mv[k].x == 0) + (mv[k].y == 0) + (mv[k].z == 0) + (mv[k].w == 0);

    #pragma unroll
    for (int off = 16; off > 0; off >>= 1)
        sum += __shfl_down_sync(0xFFFFFFFFu, sum, off);

    __shared__ int warp_sums[8];
    __shared__ int sh_L;
    const int lane = tid & 31;
    const int wid  = tid >> 5;
    if (lane == 0) warp_sums[wid] = sum;
    __syncthreads();
    if (tid == 0) {
        int v = warp_sums[0];
        #pragma unroll
        for (int w = 1; w < 8; w++) v += warp_sums[w];
        sh_L = v;
    }
    __syncthreads();
    const int L = sh_L;

    // 5) Reversed-feature pe (rows L-1-s, lanes reversed)
    #pragma unroll
    for (int k = 0; k < ILP; k++) {
        if (s_arr[k] < L) {
            const int row = L - 1 - s_arr[k];    // >= 0 because s < L
            const float4 rv = pe[row * PE_VEC_PER_ROW + (PE_VEC_PER_ROW - 1 - c4_arr[k])];
            o[k].x += rv.w;
            o[k].y += rv.z;
            o[k].z += rv.y;
            o[k].w += rv.x;
        }
    }

    // 6) Streaming stores
    #pragma unroll
    for (int k = 0; k < ILP; k++)
        __stcs(&out[base + k * 256], o[k]);
}

// ---------------------------------------------------------------------------
// d_in[0] = x (f32, 16*4096*512), d_in[1] = mask (i32, 16*4096),
// d_in[2] = pe (f32, 5000*256)
// ---------------------------------------------------------------------------
extern "C" void kernel_launch(void* const* d_in, const int* in_sizes, int n_in,
                              void* d_out, int out_size) {
    const float* x    = (const float*)d_in[0];
    const int*   mask = (const int*)d_in[1];
    const float* pe   = (const float*)d_in[2];
    float* out = (float*)d_out;

    const int total_vec = B_SZ * S_SZ * VEC_PER_ROW;        // 8,388,608
    const int blocks = total_vec / (256 * ILP);             // 8192
    fused_pe_kernel<<<blocks, 256>>>(
        (const float4*)x, (const int4*)mask, (const float4*)pe, (float4*)out);
}